// round 1
// baseline (speedup 1.0000x reference)
#include <cuda_runtime.h>

#define NN   13824      // neurons (24^3)
#define BB   256        // batch
#define DIM  512        // input dim
#define OD   1000       // output dim
#define ODP  1024       // padded output dim
#define SPLITK 8
#define KC   (NN / SPLITK)   // 1728
#define CUBE 24

// ---------------- device scratch (no allocs allowed) ----------------
__device__ float g_xp[NN * BB];            // x_proj, layout [n][b]
__device__ float g_h[2][NN * BB];          // ping-pong h, layout [n][b]
__device__ float g_part[SPLITK * BB * ODP];

__device__ __forceinline__ float tanh_acc(float x) {
    // accurate-enough tanh: (e^{2x}-1)/(e^{2x}+1) with MUFU ex2/rcp
    x = fminf(15.0f, fmaxf(-15.0f, x));
    float e = __expf(2.0f * x);
    return __fdividef(e - 1.0f, e + 1.0f);
}

// ---------------- kernel 1: x_proj = x @ W_in^T + b_in, out [n][b] ----------------
__global__ __launch_bounds__(256) void xproj_kernel(
    const float* __restrict__ X,      // [256][512]
    const float* __restrict__ W,      // [13824][512]
    const float* __restrict__ bias)   // [13824]
{
    __shared__ float As[16][68];
    __shared__ float Xs[16][68];
    int tid = threadIdx.x;
    int b0 = blockIdx.x * 64;
    int n0 = blockIdx.y * 64;
    int tb = tid & 15, tn = tid >> 4;
    int lr = tid >> 2, lc = tid & 3;
    float c[4][4];
#pragma unroll
    for (int i = 0; i < 4; i++)
#pragma unroll
        for (int j = 0; j < 4; j++) c[i][j] = 0.f;

    for (int k0 = 0; k0 < DIM; k0 += 16) {
        float4 av = *(const float4*)(W + (n0 + lr) * DIM + k0 + lc * 4);
        float4 xv = *(const float4*)(X + (b0 + lr) * DIM + k0 + lc * 4);
        __syncthreads();
        As[lc*4+0][lr] = av.x; As[lc*4+1][lr] = av.y;
        As[lc*4+2][lr] = av.z; As[lc*4+3][lr] = av.w;
        Xs[lc*4+0][lr] = xv.x; Xs[lc*4+1][lr] = xv.y;
        Xs[lc*4+2][lr] = xv.z; Xs[lc*4+3][lr] = xv.w;
        __syncthreads();
#pragma unroll
        for (int kk = 0; kk < 16; kk++) {
            float4 a4 = *(const float4*)&As[kk][tn*4];
            float4 b4 = *(const float4*)&Xs[kk][tb*4];
            float aa[4] = {a4.x, a4.y, a4.z, a4.w};
            float bb[4] = {b4.x, b4.y, b4.z, b4.w};
#pragma unroll
            for (int i = 0; i < 4; i++)
#pragma unroll
                for (int j = 0; j < 4; j++)
                    c[i][j] = fmaf(aa[i], bb[j], c[i][j]);
        }
    }
#pragma unroll
    for (int i = 0; i < 4; i++) {
        float bv = bias[n0 + tn*4 + i];
        float4 o = make_float4(c[i][0] + bv, c[i][1] + bv, c[i][2] + bv, c[i][3] + bv);
        *(float4*)(g_xp + (n0 + tn*4 + i) * BB + b0 + tb*4) = o;
    }
}

// ---------------- kernel 2: h1 = tanh(x_proj) ----------------
__global__ __launch_bounds__(256) void step0_kernel() {
    int i = blockIdx.x * 256 + threadIdx.x;
    g_h[0][i] = tanh_acc(g_xp[i]);
}

// ---------------- kernel 3: one stencil step ----------------
// block tile: x full row (24) x YT=4 y x ZT=2 z x BT=16 batch; 128 threads
__global__ __launch_bounds__(128) void step_kernel(int src, const float* __restrict__ Wl) {
    const float* __restrict__ hin = g_h[src];
    float* __restrict__ hout = g_h[src ^ 1];

    extern __shared__ float dyn[];
    float* sh  = dyn;            // [4 z][6 y][27 x(pad)][16 b] = 10368 floats
    float* wsh = dyn + 10368;    // [8 g][24 x][28 k(pad)]      = 5376 floats

    int tid = threadIdx.x;
    int y0 = blockIdx.x * 4;
    int z0 = blockIdx.y * 2;
    int b0 = blockIdx.z * 16;

    // halo load: 4x6x26 sites x 16 batch (as 4 float4)
    for (int i = tid; i < 624 * 4; i += 128) {
        int q = i & 3, site = i >> 2;
        int xx = site % 26; int t2 = site / 26;
        int yy = t2 % 6;    int zz = t2 / 6;
        int gx = xx - 1, gy = y0 + yy - 1, gz = z0 + zz - 1;
        float4 v = make_float4(0.f, 0.f, 0.f, 0.f);
        if ((unsigned)gx < (unsigned)CUBE && (unsigned)gy < (unsigned)CUBE &&
            (unsigned)gz < (unsigned)CUBE)
            v = *(const float4*)(hin + (gz * 576 + gy * 24 + gx) * BB + b0 + q * 4);
        *(float4*)(sh + ((zz * 6 + yy) * 27 + xx) * 16 + q * 4) = v;
    }
    // weight load: 8 groups x 24 x-positions x 27 weights (pad stride 28)
    for (int i = tid; i < 8 * 648; i += 128) {
        int g = i / 648, j = i % 648;
        int xw = j / 27, kw = j % 27;
        int nb2 = (z0 + (g >> 2)) * 576 + (y0 + (g & 3)) * 24;
        wsh[g * 672 + xw * 28 + kw] = Wl[(nb2 + xw) * 27 + kw];
    }
    __syncthreads();

    int b = tid & 15, g = tid >> 4;
    int gy = g & 3, gz = g >> 2;
    const float* shb = sh + b;
    int roff[9];
#pragma unroll
    for (int dz = 0; dz < 3; dz++)
#pragma unroll
        for (int dy = 0; dy < 3; dy++)
            roff[dz * 3 + dy] = (((gz + dz) * 6 + (gy + dy)) * 27) * 16;

    float v0[9], v1[9], v2[9];
#pragma unroll
    for (int r = 0; r < 9; r++) { v0[r] = shb[roff[r]]; v1[r] = shb[roff[r] + 16]; }

    int nrow = (z0 + gz) * 576 + (y0 + gy) * 24;
    const float* wq = wsh + g * 672;
    const float* xprow = g_xp + nrow * BB + b0 + b;
    float* horow = hout + nrow * BB + b0 + b;
    float xpv = xprow[0];

#pragma unroll
    for (int x = 0; x < 24; x++) {
#pragma unroll
        for (int r = 0; r < 9; r++) v2[r] = shb[roff[r] + (x + 2) * 16];
        float xpn = (x < 23) ? xprow[(x + 1) * BB] : 0.f;
        float w[28];
#pragma unroll
        for (int q = 0; q < 7; q++)
            *(float4*)(w + q * 4) = *(const float4*)(wq + x * 28 + q * 4);
        float a0 = xpv, a1 = 0.f, a2 = 0.f;
#pragma unroll
        for (int r = 0; r < 9; r++) {
            a0 = fmaf(w[r * 3 + 0], v0[r], a0);
            a1 = fmaf(w[r * 3 + 1], v1[r], a1);
            a2 = fmaf(w[r * 3 + 2], v2[r], a2);
        }
        horow[x * BB] = tanh_acc(a0 + (a1 + a2));
#pragma unroll
        for (int r = 0; r < 9; r++) { v0[r] = v1[r]; v1[r] = v2[r]; }
        xpv = xpn;
    }
}

// ---------------- kernel 4: split-K output GEMM partials ----------------
// part[sk][b][o] = sum_{n in chunk sk} h[n][b] * W_out[o][n]
__global__ __launch_bounds__(256) void outgemm_kernel(const float* __restrict__ Wo) {
    __shared__ float Hs[16][68];
    __shared__ float Ws[16][68];
    int tid = threadIdx.x;
    int b0 = blockIdx.x * 64;   // 4 tiles
    int o0 = blockIdx.y * 64;   // 16 tiles (last padded)
    int sk = blockIdx.z;        // 8 splits
    const float* __restrict__ h = g_h[1];   // final h after 30 steps

    int to = tid & 15, tb = tid >> 4;
    int hr = tid >> 4, hc = tid & 15;
    int wr = tid >> 2, wc = tid & 3;
    float c[4][4];
#pragma unroll
    for (int i = 0; i < 4; i++)
#pragma unroll
        for (int j = 0; j < 4; j++) c[i][j] = 0.f;

    for (int kt = 0; kt < KC; kt += 16) {
        int nb = sk * KC + kt;
        float4 hv = *(const float4*)(h + (nb + hr) * BB + b0 + hc * 4);
        float4 wv = make_float4(0.f, 0.f, 0.f, 0.f);
        if (o0 + wr < OD)
            wv = *(const float4*)(Wo + (o0 + wr) * NN + nb + wc * 4);
        __syncthreads();
        *(float4*)&Hs[hr][hc * 4] = hv;
        Ws[wc*4+0][wr] = wv.x; Ws[wc*4+1][wr] = wv.y;
        Ws[wc*4+2][wr] = wv.z; Ws[wc*4+3][wr] = wv.w;
        __syncthreads();
#pragma unroll
        for (int kk = 0; kk < 16; kk++) {
            float4 b4 = *(const float4*)&Hs[kk][tb * 4];
            float4 o4 = *(const float4*)&Ws[kk][to * 4];
            float bbv[4] = {b4.x, b4.y, b4.z, b4.w};
            float oov[4] = {o4.x, o4.y, o4.z, o4.w};
#pragma unroll
            for (int i = 0; i < 4; i++)
#pragma unroll
                for (int j = 0; j < 4; j++)
                    c[i][j] = fmaf(bbv[i], oov[j], c[i][j]);
        }
    }
#pragma unroll
    for (int i = 0; i < 4; i++) {
        *(float4*)(g_part + (sk * BB + b0 + tb * 4 + i) * ODP + o0 + to * 4) =
            make_float4(c[i][0], c[i][1], c[i][2], c[i][3]);
    }
}

// ---------------- kernel 5: reduce partials + bias ----------------
__global__ __launch_bounds__(256) void reduce_kernel(const float* __restrict__ bo,
                                                     float* __restrict__ out) {
    int idx = blockIdx.x * 256 + threadIdx.x;
    if (idx >= BB * OD) return;
    int b = idx / OD, o = idx % OD;
    float s = bo[o];
#pragma unroll
    for (int sk = 0; sk < SPLITK; sk++)
        s += g_part[(sk * BB + b) * ODP + o];
    out[b * OD + o] = s;
}

// ---------------- launch ----------------
extern "C" void kernel_launch(void* const* d_in, const int* in_sizes, int n_in,
                              void* d_out, int out_size) {
    const float* x   = (const float*)d_in[0];
    const float* Wi  = (const float*)d_in[1];
    const float* bi  = (const float*)d_in[2];
    const float* Wl  = (const float*)d_in[3];
    const float* Wo  = (const float*)d_in[4];
    const float* bo  = (const float*)d_in[5];
    // d_in[6] = neighbor_indices (recomputed analytically; unused)
    float* out = (float*)d_out;

    static const int STEP_SMEM = (10368 + 5376) * 4;   // 62976 bytes
    cudaFuncSetAttribute(step_kernel, cudaFuncAttributeMaxDynamicSharedMemorySize,
                         STEP_SMEM);

    // 1. x_proj
    xproj_kernel<<<dim3(BB / 64, NN / 64), 256>>>(x, Wi, bi);
    // 2. h1 = tanh(x_proj)
    step0_kernel<<<NN * BB / 256, 256>>>();
    // 3. 29 stencil steps (total 30 applications); final lands in g_h[1]
    int src = 0;
    for (int s = 0; s < 29; s++) {
        step_kernel<<<dim3(CUBE / 4, CUBE / 2, BB / 16), 128, STEP_SMEM>>>(src, Wl);
        src ^= 1;
    }
    // 4. output GEMM (split-K partials), 5. reduce + bias
    outgemm_kernel<<<dim3(BB / 64, 16, SPLITK), 256>>>(Wo);
    reduce_kernel<<<(BB * OD + 255) / 256, 256>>>(bo, out);
}

// round 2
// speedup vs baseline: 1.1351x; 1.1351x over previous
#include <cuda_runtime.h>

#define NN   13824      // neurons (24^3)
#define BB   256        // batch
#define DIM  512        // input dim
#define OD   1000       // output dim
#define ODP  1024       // padded output dim
#define SPLITK 8
#define KC   (NN / SPLITK)   // 1728
#define CUBE 24

// step kernel tiling
#define YS   424                   // halo y stride (floats): 26*16 + 8 pad
#define ZSH  (10 * YS)             // halo z stride = 4240
#define WS   680                   // weight row stride (floats): 24*28 + 8 pad
#define HALO_FLOATS (4 * ZSH)      // 16960
#define WSH_FLOATS  (16 * WS)      // 10880
#define STEP_SMEM  ((HALO_FLOATS + WSH_FLOATS) * 4)   // 111360 bytes

// ---------------- device scratch (no allocs allowed) ----------------
__device__ float g_xp[NN * BB];            // x_proj, layout [n][b]
__device__ float g_h[2][NN * BB];          // ping-pong h, layout [n][b]
__device__ float g_part[SPLITK * BB * ODP];

__device__ __forceinline__ float tanh_acc(float x) {
    x = fminf(15.0f, fmaxf(-15.0f, x));
    float e = __expf(2.0f * x);
    return __fdividef(e - 1.0f, e + 1.0f);
}

// ---------------- kernel 1: x_proj = x @ W_in^T + b_in, out [n][b] ----------------
__global__ __launch_bounds__(256) void xproj_kernel(
    const float* __restrict__ X,      // [256][512]
    const float* __restrict__ W,      // [13824][512]
    const float* __restrict__ bias)   // [13824]
{
    __shared__ float As[16][68];
    __shared__ float Xs[16][68];
    int tid = threadIdx.x;
    int b0 = blockIdx.x * 64;
    int n0 = blockIdx.y * 64;
    int tb = tid & 15, tn = tid >> 4;
    int lr = tid >> 2, lc = tid & 3;
    float c[4][4];
#pragma unroll
    for (int i = 0; i < 4; i++)
#pragma unroll
        for (int j = 0; j < 4; j++) c[i][j] = 0.f;

    for (int k0 = 0; k0 < DIM; k0 += 16) {
        float4 av = *(const float4*)(W + (n0 + lr) * DIM + k0 + lc * 4);
        float4 xv = *(const float4*)(X + (b0 + lr) * DIM + k0 + lc * 4);
        __syncthreads();
        As[lc*4+0][lr] = av.x; As[lc*4+1][lr] = av.y;
        As[lc*4+2][lr] = av.z; As[lc*4+3][lr] = av.w;
        Xs[lc*4+0][lr] = xv.x; Xs[lc*4+1][lr] = xv.y;
        Xs[lc*4+2][lr] = xv.z; Xs[lc*4+3][lr] = xv.w;
        __syncthreads();
#pragma unroll
        for (int kk = 0; kk < 16; kk++) {
            float4 a4 = *(const float4*)&As[kk][tn*4];
            float4 b4 = *(const float4*)&Xs[kk][tb*4];
            float aa[4] = {a4.x, a4.y, a4.z, a4.w};
            float bb[4] = {b4.x, b4.y, b4.z, b4.w};
#pragma unroll
            for (int i = 0; i < 4; i++)
#pragma unroll
                for (int j = 0; j < 4; j++)
                    c[i][j] = fmaf(aa[i], bb[j], c[i][j]);
        }
    }
#pragma unroll
    for (int i = 0; i < 4; i++) {
        float bv = bias[n0 + tn*4 + i];
        float4 o = make_float4(c[i][0] + bv, c[i][1] + bv, c[i][2] + bv, c[i][3] + bv);
        *(float4*)(g_xp + (n0 + tn*4 + i) * BB + b0 + tb*4) = o;
    }
}

// ---------------- kernel 2: h1 = tanh(x_proj) ----------------
__global__ __launch_bounds__(256) void step0_kernel() {
    int i = blockIdx.x * 256 + threadIdx.x;
    g_h[0][i] = tanh_acc(g_xp[i]);
}

// ---------------- kernel 3: one stencil step (float4 over batch) ----------------
// tile: 8y x 2z x 24x x 16 batch; 128 threads
// thread map: q = tid&3 (batch quad), ry = (tid>>2)&7, warp = tid>>5 -> xh = w&1, rz = w>>1
__global__ __launch_bounds__(128, 2) void step_kernel(int src, const float* __restrict__ Wl) {
    const float* __restrict__ hin = g_h[src];
    float* __restrict__ hout = g_h[src ^ 1];

    extern __shared__ float dyn[];
    float* sh  = dyn;                 // halo [4z][10y][26x][16b] padded
    float* wsh = dyn + HALO_FLOATS;   // weights [16 rows][24x][27] padded

    int tid = threadIdx.x;
    int y0 = blockIdx.x * 8;
    int z0 = blockIdx.y * 2;
    int b0 = blockIdx.z * 16;

    // halo load: 4z x 10y x 26x sites, 4 float4 each = 4160 float4
    for (int i = tid; i < 4160; i += 128) {
        int q = i & 3; int site = i >> 2;
        int xx = site % 26; int t2 = site / 26;
        int yy = t2 % 10;   int zz = t2 / 10;
        int gx = xx - 1, gy = y0 + yy - 1, gz = z0 + zz - 1;
        float4 v = make_float4(0.f, 0.f, 0.f, 0.f);
        if ((unsigned)gx < (unsigned)CUBE && (unsigned)gy < (unsigned)CUBE &&
            (unsigned)gz < (unsigned)CUBE)
            v = *(const float4*)(hin + (gz * 576 + gy * 24 + gx) * BB + b0 + q * 4);
        *(float4*)(sh + zz * ZSH + yy * YS + xx * 16 + q * 4) = v;
    }
    // weight load: 16 rows x 648 floats
    for (int i = tid; i < 16 * 648; i += 128) {
        int r = i / 648, j = i % 648;
        int x = j / 27, k = j % 27;
        int nr = (z0 + (r >> 3)) * 576 + (y0 + (r & 7)) * 24;
        wsh[r * WS + x * 28 + k] = Wl[(nr + x) * 27 + k];
    }
    __syncthreads();

    int q  = tid & 3;
    int ry = (tid >> 2) & 7;
    int wp = tid >> 5;
    int xh = wp & 1, rz = wp >> 1;
    int x0 = xh * 12;

    int roff[9];
#pragma unroll
    for (int dz = 0; dz < 3; dz++)
#pragma unroll
        for (int dy = 0; dy < 3; dy++)
            roff[dz * 3 + dy] = (rz + dz) * ZSH + (ry + dy) * YS + q * 4;

    float4 v0[9], v1[9];
#pragma unroll
    for (int r = 0; r < 9; r++) {
        v0[r] = *(const float4*)(sh + roff[r] + x0 * 16);
        v1[r] = *(const float4*)(sh + roff[r] + (x0 + 1) * 16);
    }

    int nrow = (z0 + rz) * 576 + (y0 + ry) * 24;
    const float* wq = wsh + (ry + 8 * rz) * WS;
    const float* xprow = g_xp + (nrow + x0) * BB + b0 + q * 4;
    float* horow = hout + (nrow + x0) * BB + b0 + q * 4;
    float4 xpv = *(const float4*)xprow;

#pragma unroll
    for (int xi = 0; xi < 12; xi++) {
        int x = x0 + xi;
        // prefetch next xp row
        float4 xpn = make_float4(0.f, 0.f, 0.f, 0.f);
        if (x < 23) xpn = *(const float4*)(xprow + (xi + 1) * BB);

        float wv[28];
#pragma unroll
        for (int t = 0; t < 7; t++)
            *(float4*)(wv + t * 4) = *(const float4*)(wq + x * 28 + t * 4);

        float4 a0 = xpv;
        float4 a1 = make_float4(0.f, 0.f, 0.f, 0.f);
        float4 a2 = make_float4(0.f, 0.f, 0.f, 0.f);
#pragma unroll
        for (int r = 0; r < 9; r++) {
            float w0 = wv[r * 3 + 0], w1 = wv[r * 3 + 1], w2 = wv[r * 3 + 2];
            a0.x = fmaf(w0, v0[r].x, a0.x); a0.y = fmaf(w0, v0[r].y, a0.y);
            a0.z = fmaf(w0, v0[r].z, a0.z); a0.w = fmaf(w0, v0[r].w, a0.w);
            a1.x = fmaf(w1, v1[r].x, a1.x); a1.y = fmaf(w1, v1[r].y, a1.y);
            a1.z = fmaf(w1, v1[r].z, a1.z); a1.w = fmaf(w1, v1[r].w, a1.w);
            float4 t = *(const float4*)(sh + roff[r] + (x + 2) * 16);
            a2.x = fmaf(w2, t.x, a2.x); a2.y = fmaf(w2, t.y, a2.y);
            a2.z = fmaf(w2, t.z, a2.z); a2.w = fmaf(w2, t.w, a2.w);
            v0[r] = v1[r]; v1[r] = t;
        }
        float4 o;
        o.x = tanh_acc(a0.x + (a1.x + a2.x));
        o.y = tanh_acc(a0.y + (a1.y + a2.y));
        o.z = tanh_acc(a0.z + (a1.z + a2.z));
        o.w = tanh_acc(a0.w + (a1.w + a2.w));
        *(float4*)(horow + xi * BB) = o;
        xpv = xpn;
    }
}

// ---------------- kernel 4: split-K output GEMM partials ----------------
__global__ __launch_bounds__(256) void outgemm_kernel(const float* __restrict__ Wo) {
    __shared__ float Hs[16][68];
    __shared__ float Ws[16][68];
    int tid = threadIdx.x;
    int b0 = blockIdx.x * 64;
    int o0 = blockIdx.y * 64;
    int sk = blockIdx.z;
    const float* __restrict__ h = g_h[1];

    int to = tid & 15, tb = tid >> 4;
    int hr = tid >> 4, hc = tid & 15;
    int wr = tid >> 2, wc = tid & 3;
    float c[4][4];
#pragma unroll
    for (int i = 0; i < 4; i++)
#pragma unroll
        for (int j = 0; j < 4; j++) c[i][j] = 0.f;

    for (int kt = 0; kt < KC; kt += 16) {
        int nb = sk * KC + kt;
        float4 hv = *(const float4*)(h + (nb + hr) * BB + b0 + hc * 4);
        float4 wv = make_float4(0.f, 0.f, 0.f, 0.f);
        if (o0 + wr < OD)
            wv = *(const float4*)(Wo + (o0 + wr) * NN + nb + wc * 4);
        __syncthreads();
        *(float4*)&Hs[hr][hc * 4] = hv;
        Ws[wc*4+0][wr] = wv.x; Ws[wc*4+1][wr] = wv.y;
        Ws[wc*4+2][wr] = wv.z; Ws[wc*4+3][wr] = wv.w;
        __syncthreads();
#pragma unroll
        for (int kk = 0; kk < 16; kk++) {
            float4 b4 = *(const float4*)&Hs[kk][tb * 4];
            float4 o4 = *(const float4*)&Ws[kk][to * 4];
            float bbv[4] = {b4.x, b4.y, b4.z, b4.w};
            float oov[4] = {o4.x, o4.y, o4.z, o4.w};
#pragma unroll
            for (int i = 0; i < 4; i++)
#pragma unroll
                for (int j = 0; j < 4; j++)
                    c[i][j] = fmaf(bbv[i], oov[j], c[i][j]);
        }
    }
#pragma unroll
    for (int i = 0; i < 4; i++) {
        *(float4*)(g_part + (sk * BB + b0 + tb * 4 + i) * ODP + o0 + to * 4) =
            make_float4(c[i][0], c[i][1], c[i][2], c[i][3]);
    }
}

// ---------------- kernel 5: reduce partials + bias ----------------
__global__ __launch_bounds__(256) void reduce_kernel(const float* __restrict__ bo,
                                                     float* __restrict__ out) {
    int idx = blockIdx.x * 256 + threadIdx.x;
    if (idx >= BB * OD) return;
    int b = idx / OD, o = idx % OD;
    float s = bo[o];
#pragma unroll
    for (int sk = 0; sk < SPLITK; sk++)
        s += g_part[(sk * BB + b) * ODP + o];
    out[b * OD + o] = s;
}

// ---------------- launch ----------------
extern "C" void kernel_launch(void* const* d_in, const int* in_sizes, int n_in,
                              void* d_out, int out_size) {
    const float* x   = (const float*)d_in[0];
    const float* Wi  = (const float*)d_in[1];
    const float* bi  = (const float*)d_in[2];
    const float* Wl  = (const float*)d_in[3];
    const float* Wo  = (const float*)d_in[4];
    const float* bo  = (const float*)d_in[5];
    float* out = (float*)d_out;

    cudaFuncSetAttribute(step_kernel, cudaFuncAttributeMaxDynamicSharedMemorySize,
                         STEP_SMEM);

    xproj_kernel<<<dim3(BB / 64, NN / 64), 256>>>(x, Wi, bi);
    step0_kernel<<<NN * BB / 256, 256>>>();

    int src = 0;
    for (int s = 0; s < 29; s++) {
        step_kernel<<<dim3(CUBE / 8, CUBE / 2, BB / 16), 128, STEP_SMEM>>>(src, Wl);
        src ^= 1;
    }

    outgemm_kernel<<<dim3(BB / 64, 16, SPLITK), 256>>>(Wo);
    reduce_kernel<<<(BB * OD + 255) / 256, 256>>>(bo, out);
}

// round 3
// speedup vs baseline: 1.3895x; 1.2241x over previous
#include <cuda_runtime.h>

#define NN   13824
#define BB   256
#define DIM  512
#define OD   1000
#define ODP  1024
#define SK   16
#define KCHUNK (NN / SK)       // 864
#define CUBE 24

// step kernel smem geometry
#define YS   432               // halo y stride (floats): 26*16 + 16 pad (bank step 16)
#define ZS   (10 * YS)         // 4320
#define HALO_F (4 * ZS)        // 17280
#define WROW 676               // weight row stride (24*28 + 4 pad -> bank step 4)
#define WSH_F (16 * WROW)      // 10816
#define STEP_SMEM ((HALO_F + WSH_F) * 4)   // 112384 bytes

// ---------------- device scratch ----------------
__device__ float g_xp[NN * BB];
__device__ float g_h[2][NN * BB];
__device__ float g_part[SK * BB * ODP];

__device__ __forceinline__ float tanh_acc(float x) {
    x = fminf(15.0f, fmaxf(-15.0f, x));
    float e = __expf(2.0f * x);
    return __fdividef(e - 1.0f, e + 1.0f);
}

// ---------------- kernel 1: x_proj = x @ W_in^T + b, out [n][b] ----------------
// 128(n) x 128(b) tile, 256 threads, 8x8 per thread
__global__ __launch_bounds__(256) void xproj_kernel(
    const float* __restrict__ X, const float* __restrict__ W,
    const float* __restrict__ bias)
{
    __shared__ float As[16][132];
    __shared__ float Bs[16][132];
    int tid = threadIdx.x;
    int b0 = blockIdx.x * 128;
    int n0 = blockIdx.y * 128;
    int lr = tid >> 2, lk = (tid & 3) * 4;
    int tn = tid >> 4, tb = tid & 15;
    float acc[8][8];
#pragma unroll
    for (int i = 0; i < 8; i++)
#pragma unroll
        for (int j = 0; j < 8; j++) acc[i][j] = 0.f;

    for (int k0 = 0; k0 < DIM; k0 += 16) {
        float4 a0 = *(const float4*)(W + (n0 + lr) * DIM + k0 + lk);
        float4 a1 = *(const float4*)(W + (n0 + lr + 64) * DIM + k0 + lk);
        float4 x0 = *(const float4*)(X + (b0 + lr) * DIM + k0 + lk);
        float4 x1 = *(const float4*)(X + (b0 + lr + 64) * DIM + k0 + lk);
        __syncthreads();
        As[lk+0][lr] = a0.x; As[lk+1][lr] = a0.y; As[lk+2][lr] = a0.z; As[lk+3][lr] = a0.w;
        As[lk+0][lr+64] = a1.x; As[lk+1][lr+64] = a1.y; As[lk+2][lr+64] = a1.z; As[lk+3][lr+64] = a1.w;
        Bs[lk+0][lr] = x0.x; Bs[lk+1][lr] = x0.y; Bs[lk+2][lr] = x0.z; Bs[lk+3][lr] = x0.w;
        Bs[lk+0][lr+64] = x1.x; Bs[lk+1][lr+64] = x1.y; Bs[lk+2][lr+64] = x1.z; Bs[lk+3][lr+64] = x1.w;
        __syncthreads();
#pragma unroll
        for (int kk = 0; kk < 16; kk++) {
            float4 aA = *(const float4*)&As[kk][tn * 4];
            float4 aB = *(const float4*)&As[kk][64 + tn * 4];
            float4 bA = *(const float4*)&Bs[kk][tb * 4];
            float4 bB = *(const float4*)&Bs[kk][64 + tb * 4];
            float ar[8] = {aA.x, aA.y, aA.z, aA.w, aB.x, aB.y, aB.z, aB.w};
            float br[8] = {bA.x, bA.y, bA.z, bA.w, bB.x, bB.y, bB.z, bB.w};
#pragma unroll
            for (int i = 0; i < 8; i++)
#pragma unroll
                for (int j = 0; j < 8; j++)
                    acc[i][j] = fmaf(ar[i], br[j], acc[i][j]);
        }
    }
#pragma unroll
    for (int i = 0; i < 8; i++) {
        int n = n0 + (i < 4 ? tn * 4 + i : 64 + tn * 4 + i - 4);
        float bv = bias[n];
        *(float4*)(g_xp + n * BB + b0 + tb * 4) =
            make_float4(acc[i][0]+bv, acc[i][1]+bv, acc[i][2]+bv, acc[i][3]+bv);
        *(float4*)(g_xp + n * BB + b0 + 64 + tb * 4) =
            make_float4(acc[i][4]+bv, acc[i][5]+bv, acc[i][6]+bv, acc[i][7]+bv);
    }
}

// ---------------- kernel 2: h1 = tanh(x_proj) ----------------
__global__ __launch_bounds__(256) void step0_kernel() {
    int i = blockIdx.x * 256 + threadIdx.x;
    g_h[0][i] = tanh_acc(g_xp[i]);
}

// ---------------- kernel 3: stencil step ----------------
// 256 threads: q=tid&3 (batch quad), ry=(tid>>2)&7, rz=(tid>>5)&1, xq=tid>>6
// tile 8y x 2z x 24x x 16b
__global__ __launch_bounds__(256, 2) void step_kernel(int src, const float* __restrict__ Wl) {
    const float* __restrict__ hin = g_h[src];
    float* __restrict__ hout = g_h[src ^ 1];

    extern __shared__ float dyn[];
    float* sh  = dyn;             // halo [4z][10y][26x][16b]
    float* wsh = dyn + HALO_F;    // weights [16 rows][24x][28]

    int tid = threadIdx.x;
    int y0 = blockIdx.x * 8;
    int z0 = blockIdx.y * 2;
    int b0 = blockIdx.z * 16;

    // halo: 4z x 10y x 26x sites x 4 quads = 4160 float4
    for (int i = tid; i < 4160; i += 256) {
        int q = i & 3; int site = i >> 2;
        int xx = site % 26; int t2 = site / 26;
        int yy = t2 % 10;   int zz = t2 / 10;
        int gx = xx - 1, gy = y0 + yy - 1, gz = z0 + zz - 1;
        float4 v = make_float4(0.f, 0.f, 0.f, 0.f);
        if ((unsigned)gx < (unsigned)CUBE && (unsigned)gy < (unsigned)CUBE &&
            (unsigned)gz < (unsigned)CUBE)
            v = *(const float4*)(hin + (gz * 576 + gy * 24 + gx) * BB + b0 + q * 4);
        *(float4*)(sh + zz * ZS + yy * YS + xx * 16 + q * 4) = v;
    }
    // weights: 16 rows x 648
    for (int i = tid; i < 16 * 648; i += 256) {
        int r = i / 648, j = i % 648;
        int x = j / 27, k = j % 27;
        int nr = (z0 + (r >> 3)) * 576 + (y0 + (r & 7)) * 24;
        wsh[r * WROW + x * 28 + k] = Wl[(nr + x) * 27 + k];
    }
    __syncthreads();

    int q  = tid & 3;
    int ry = (tid >> 2) & 7;
    int rz = (tid >> 5) & 1;
    int xq = tid >> 6;
    int x0 = xq * 6;

    int roff[9];
#pragma unroll
    for (int dz = 0; dz < 3; dz++)
#pragma unroll
        for (int dy = 0; dy < 3; dy++)
            roff[dz * 3 + dy] = (rz + dz) * ZS + (ry + dy) * YS + q * 4;

    float4 v0[9], v1[9];
#pragma unroll
    for (int r = 0; r < 9; r++) {
        v0[r] = *(const float4*)(sh + roff[r] + x0 * 16);
        v1[r] = *(const float4*)(sh + roff[r] + (x0 + 1) * 16);
    }

    int nrow = (z0 + rz) * 576 + (y0 + ry) * 24;
    const float* wq = wsh + (rz * 8 + ry) * WROW;
    const float* xprow = g_xp + (nrow + x0) * BB + b0 + q * 4;
    float* horow = hout + (nrow + x0) * BB + b0 + q * 4;
    float4 xpv = *(const float4*)xprow;

#pragma unroll
    for (int xi = 0; xi < 6; xi++) {
        int x = x0 + xi;
        float4 xpn = make_float4(0.f, 0.f, 0.f, 0.f);
        if (x < 23) xpn = *(const float4*)(xprow + (xi + 1) * BB);

        float wv[28];
#pragma unroll
        for (int t = 0; t < 7; t++)
            *(float4*)(wv + t * 4) = *(const float4*)(wq + x * 28 + t * 4);

        float4 a0 = xpv;
        float4 a1 = make_float4(0.f, 0.f, 0.f, 0.f);
        float4 a2 = make_float4(0.f, 0.f, 0.f, 0.f);
#pragma unroll
        for (int r = 0; r < 9; r++) {
            float w0 = wv[r*3+0], w1 = wv[r*3+1], w2 = wv[r*3+2];
            a0.x = fmaf(w0, v0[r].x, a0.x); a0.y = fmaf(w0, v0[r].y, a0.y);
            a0.z = fmaf(w0, v0[r].z, a0.z); a0.w = fmaf(w0, v0[r].w, a0.w);
            a1.x = fmaf(w1, v1[r].x, a1.x); a1.y = fmaf(w1, v1[r].y, a1.y);
            a1.z = fmaf(w1, v1[r].z, a1.z); a1.w = fmaf(w1, v1[r].w, a1.w);
            float4 t = *(const float4*)(sh + roff[r] + (x + 2) * 16);
            a2.x = fmaf(w2, t.x, a2.x); a2.y = fmaf(w2, t.y, a2.y);
            a2.z = fmaf(w2, t.z, a2.z); a2.w = fmaf(w2, t.w, a2.w);
            v0[r] = v1[r]; v1[r] = t;
        }
        float4 o;
        o.x = tanh_acc(a0.x + (a1.x + a2.x));
        o.y = tanh_acc(a0.y + (a1.y + a2.y));
        o.z = tanh_acc(a0.z + (a1.z + a2.z));
        o.w = tanh_acc(a0.w + (a1.w + a2.w));
        *(float4*)(horow + xi * BB) = o;
        xpv = xpn;
    }
}

// ---------------- kernel 4: split-K output GEMM ----------------
// C[b][o], 128b x 128o tile, 256 threads, 8x8/thread, K chunk 864
__global__ __launch_bounds__(256) void outgemm_kernel(const float* __restrict__ Wo) {
    __shared__ float Hs[16][132];
    __shared__ float Ws[16][132];
    const float* __restrict__ h = g_h[1];
    int tid = threadIdx.x;
    int o0 = blockIdx.x * 128;
    int b0 = blockIdx.y * 128;
    int sk = blockIdx.z;
    int nbase = sk * KCHUNK;

    int hr = tid >> 4, hc = (tid & 15) * 8;
    int wr = tid >> 2, wk = (tid & 3) * 4;
    int tb = tid >> 4, to = tid & 15;

    float acc[8][8];
#pragma unroll
    for (int i = 0; i < 8; i++)
#pragma unroll
        for (int j = 0; j < 8; j++) acc[i][j] = 0.f;

    for (int kt = 0; kt < KCHUNK / 16; kt++) {
        int nb = nbase + kt * 16;
        float4 h0 = *(const float4*)(h + (nb + hr) * BB + b0 + hc);
        float4 h1 = *(const float4*)(h + (nb + hr) * BB + b0 + hc + 4);
        float4 w0 = make_float4(0.f,0.f,0.f,0.f), w1 = make_float4(0.f,0.f,0.f,0.f);
        if (o0 + wr < OD)      w0 = *(const float4*)(Wo + (o0 + wr) * NN + nb + wk);
        if (o0 + wr + 64 < OD) w1 = *(const float4*)(Wo + (o0 + wr + 64) * NN + nb + wk);
        __syncthreads();
        *(float4*)&Hs[hr][hc] = h0;
        *(float4*)&Hs[hr][hc + 4] = h1;
        Ws[wk+0][wr] = w0.x; Ws[wk+1][wr] = w0.y; Ws[wk+2][wr] = w0.z; Ws[wk+3][wr] = w0.w;
        Ws[wk+0][wr+64] = w1.x; Ws[wk+1][wr+64] = w1.y; Ws[wk+2][wr+64] = w1.z; Ws[wk+3][wr+64] = w1.w;
        __syncthreads();
#pragma unroll
        for (int kk = 0; kk < 16; kk++) {
            float4 bA = *(const float4*)&Hs[kk][tb * 4];
            float4 bB = *(const float4*)&Hs[kk][64 + tb * 4];
            float4 oA = *(const float4*)&Ws[kk][to * 4];
            float4 oB = *(const float4*)&Ws[kk][64 + to * 4];
            float br[8] = {bA.x, bA.y, bA.z, bA.w, bB.x, bB.y, bB.z, bB.w};
            float orr[8] = {oA.x, oA.y, oA.z, oA.w, oB.x, oB.y, oB.z, oB.w};
#pragma unroll
            for (int i = 0; i < 8; i++)
#pragma unroll
                for (int j = 0; j < 8; j++)
                    acc[i][j] = fmaf(br[i], orr[j], acc[i][j]);
        }
    }
#pragma unroll
    for (int i = 0; i < 8; i++) {
        int b = b0 + (i < 4 ? tb * 4 + i : 64 + tb * 4 + i - 4);
        *(float4*)(g_part + (sk * BB + b) * ODP + o0 + to * 4) =
            make_float4(acc[i][0], acc[i][1], acc[i][2], acc[i][3]);
        *(float4*)(g_part + (sk * BB + b) * ODP + o0 + 64 + to * 4) =
            make_float4(acc[i][4], acc[i][5], acc[i][6], acc[i][7]);
    }
}

// ---------------- kernel 5: reduce partials + bias ----------------
__global__ __launch_bounds__(256) void reduce_kernel(const float* __restrict__ bo,
                                                     float* __restrict__ out) {
    int idx = blockIdx.x * 256 + threadIdx.x;
    if (idx >= BB * OD) return;
    int b = idx / OD, o = idx % OD;
    float s = bo[o];
#pragma unroll
    for (int sk = 0; sk < SK; sk++)
        s += g_part[(sk * BB + b) * ODP + o];
    out[b * OD + o] = s;
}

// ---------------- launch ----------------
extern "C" void kernel_launch(void* const* d_in, const int* in_sizes, int n_in,
                              void* d_out, int out_size) {
    const float* x   = (const float*)d_in[0];
    const float* Wi  = (const float*)d_in[1];
    const float* bi  = (const float*)d_in[2];
    const float* Wl  = (const float*)d_in[3];
    const float* Wo  = (const float*)d_in[4];
    const float* bo  = (const float*)d_in[5];
    float* out = (float*)d_out;

    cudaFuncSetAttribute(step_kernel, cudaFuncAttributeMaxDynamicSharedMemorySize,
                         STEP_SMEM);

    xproj_kernel<<<dim3(BB / 128, NN / 128), 256>>>(x, Wi, bi);
    step0_kernel<<<NN * BB / 256, 256>>>();

    int src = 0;
    for (int s = 0; s < 29; s++) {
        step_kernel<<<dim3(CUBE / 8, CUBE / 2, BB / 16), 256, STEP_SMEM>>>(src, Wl);
        src ^= 1;
    }

    outgemm_kernel<<<dim3(ODP / 128, BB / 128, SK), 256>>>(Wo);
    reduce_kernel<<<(BB * OD + 255) / 256, 256>>>(bo, out);
}

// round 4
// speedup vs baseline: 1.4732x; 1.0603x over previous
#include <cuda_runtime.h>
#include <cuda_bf16.h>

#define NN   13824
#define BB   256
#define DIM  512
#define OD   1000
#define ODP  1024
#define SK   12
#define KC   (NN / SK)         // 1152
#define CUBE 24

// ---- stencil smem geometry ----
#define YS   432
#define ZS   (10 * YS)
#define HALO_F (4 * ZS)        // 17280
#define WROW 676
#define WSH_F (16 * WROW)      // 10816
#define STEP_SMEM ((HALO_F + WSH_F) * 4)

// ---- GEMM smem geometry (bf16 units) ----
#define AS_STRIDE 72           // 64 k + 8 pad
#define BS_STRIDE 136          // 128 n + 8 pad
#define AS_PLANE  (128 * AS_STRIDE)   // 9216
#define BS_PLANE  (64 * BS_STRIDE)    // 8704
#define BS_OFF    (2 * AS_PLANE)      // 18432
#define GEMM_SMEM ((2 * AS_PLANE + 2 * BS_PLANE) * 2)  // 71680 bytes

// ---------------- device scratch ----------------
__device__ float g_xp[NN * BB];
__device__ float g_h[2][NN * BB];
__device__ float g_part[SK * BB * ODP];
__device__ __nv_bfloat16 g_WinH[NN * DIM], g_WinL[NN * DIM];
__device__ __nv_bfloat16 g_xTH[DIM * BB],  g_xTL[DIM * BB];
__device__ __nv_bfloat16 g_WoH[OD * NN],   g_WoL[OD * NN];
__device__ __nv_bfloat16 g_hH[NN * BB],    g_hL[NN * BB];

__device__ __forceinline__ float tanh_acc(float x) {
    x = fminf(15.0f, fmaxf(-15.0f, x));
    float e = __expf(2.0f * x);
    return __fdividef(e - 1.0f, e + 1.0f);
}

// ---------------- split conversion kernels ----------------
__global__ __launch_bounds__(256) void split_kernel(const float* __restrict__ s,
                                                    __nv_bfloat16* __restrict__ hi,
                                                    __nv_bfloat16* __restrict__ lo, int n) {
    int i = blockIdx.x * 256 + threadIdx.x;
    if (i >= n) return;
    float v = s[i];
    __nv_bfloat16 h = __float2bfloat16_rn(v);
    hi[i] = h;
    lo[i] = __float2bfloat16_rn(v - __bfloat162float(h));
}

// x[b][k] -> xT[k][b] split
__global__ __launch_bounds__(256) void split_xT_kernel(const float* __restrict__ x) {
    int i = blockIdx.x * 256 + threadIdx.x;   // i = k*BB + b
    if (i >= DIM * BB) return;
    int k = i / BB, b = i % BB;
    float v = x[b * DIM + k];
    __nv_bfloat16 h = __float2bfloat16_rn(v);
    g_xTH[i] = h;
    g_xTL[i] = __float2bfloat16_rn(v - __bfloat162float(h));
}

// ---------------- mma helpers ----------------
__device__ __forceinline__ void ldsm4(unsigned* r, unsigned addr) {
    asm volatile("ldmatrix.sync.aligned.m8n8.x4.shared.b16 {%0,%1,%2,%3},[%4];"
                 : "=r"(r[0]), "=r"(r[1]), "=r"(r[2]), "=r"(r[3]) : "r"(addr));
}
__device__ __forceinline__ void ldsm4t(unsigned* r, unsigned addr) {
    asm volatile("ldmatrix.sync.aligned.m8n8.x4.trans.shared.b16 {%0,%1,%2,%3},[%4];"
                 : "=r"(r[0]), "=r"(r[1]), "=r"(r[2]), "=r"(r[3]) : "r"(addr));
}
__device__ __forceinline__ void mma_bf16(float* c, const unsigned* a, const unsigned* b) {
    asm volatile("mma.sync.aligned.m16n8k16.row.col.f32.bf16.bf16.f32 "
                 "{%0,%1,%2,%3},{%4,%5,%6,%7},{%8,%9},{%0,%1,%2,%3};"
                 : "+f"(c[0]), "+f"(c[1]), "+f"(c[2]), "+f"(c[3])
                 : "r"(a[0]), "r"(a[1]), "r"(a[2]), "r"(a[3]), "r"(b[0]), "r"(b[1]));
}
__device__ __forceinline__ void cpa16(unsigned s, const void* g, int zs) {
    asm volatile("cp.async.ca.shared.global [%0],[%1],16,%2;" :: "r"(s), "l"(g), "r"(zs));
}
__device__ __forceinline__ void cpa_wait() {
    asm volatile("cp.async.commit_group;\ncp.async.wait_group 0;" ::: "memory");
}

// ---------------- split-precision bf16 MMA GEMM ----------------
// C[m][n] = sum_k A[m][k]*B[k][n], A = Ah+Al, B = Bh+Bl (drop Al*Bl)
// MODE 0: xproj  -> g_xp[m*BB+n] + bias[m]
// MODE 1: outgemm-> g_part[(sk*BB+n)*ODP+m]   (A rows >= OD zero-filled)
template<int MODE>
__global__ __launch_bounds__(256, 2) void mma_gemm(
    const __nv_bfloat16* __restrict__ Ah, const __nv_bfloat16* __restrict__ Al,
    const __nv_bfloat16* __restrict__ Bh, const __nv_bfloat16* __restrict__ Bl,
    const float* __restrict__ bias, int lda, int kstages)
{
    extern __shared__ __nv_bfloat16 smem[];
    unsigned sbase = (unsigned)__cvta_generic_to_shared(smem);

    int tid = threadIdx.x;
    int m0 = blockIdx.x * 128, n0 = blockIdx.y * 128;
    int kbase = blockIdx.z * kstages * 64;
    int warp = tid >> 5, lane = tid & 31;
    int wm = warp >> 1, wn = warp & 1;

    float acc[2][8][4];
#pragma unroll
    for (int i = 0; i < 2; i++)
#pragma unroll
        for (int j = 0; j < 8; j++)
#pragma unroll
            for (int t = 0; t < 4; t++) acc[i][j][t] = 0.f;

    // staging indices
    int ar = tid >> 1, acu = (tid & 1) * 4;       // A: row, unit base (8 bf16 units)
    int br = tid >> 2, bcu = (tid & 3) * 4;       // B
    int okA = (MODE == 0) || (m0 + ar < OD);
    int zsA = okA ? 16 : 0;
    unsigned sA = sbase + 2u * (unsigned)(ar * AS_STRIDE + acu * 8);
    unsigned sB = sbase + 2u * (unsigned)(BS_OFF + br * BS_STRIDE + bcu * 8);

    // ldmatrix lane address components
    int lrow = ((lane >> 3) & 1) * 8 + (lane & 7);
    int lcol = (lane >> 4) * 8;

    for (int st = 0; st < kstages; st++) {
        int kg = kbase + st * 64;
        __syncthreads();   // previous stage fully consumed
        {
            const __nv_bfloat16* gAh = Ah + (size_t)(m0 + ar) * lda + kg + acu * 8;
            const __nv_bfloat16* gAl = Al + (size_t)(m0 + ar) * lda + kg + acu * 8;
            const __nv_bfloat16* gBh = Bh + (size_t)(kg + br) * BB + n0 + bcu * 8;
            const __nv_bfloat16* gBl = Bl + (size_t)(kg + br) * BB + n0 + bcu * 8;
#pragma unroll
            for (int j = 0; j < 4; j++) {
                cpa16(sA + j * 16, gAh + j * 8, zsA);
                cpa16(sA + 2 * AS_PLANE + j * 16, gAl + j * 8, zsA);
                cpa16(sB + j * 16, gBh + j * 8, 16);
                cpa16(sB + 2 * BS_PLANE + j * 16, gBl + j * 8, 16);
            }
        }
        cpa_wait();
        __syncthreads();

#pragma unroll
        for (int ks = 0; ks < 4; ks++) {
            int ks16 = ks * 16;
            unsigned a_h[2][4], a_l[2][4];
#pragma unroll
            for (int mt = 0; mt < 2; mt++) {
                unsigned aaddr = sbase +
                    2u * (unsigned)((wm * 32 + mt * 16 + lrow) * AS_STRIDE + ks16 + lcol);
                ldsm4(a_h[mt], aaddr);
                ldsm4(a_l[mt], aaddr + 2 * AS_PLANE);
            }
#pragma unroll
            for (int np = 0; np < 4; np++) {
                unsigned b_h[4], b_l[4];
                unsigned baddr = sbase +
                    2u * (unsigned)(BS_OFF + (ks16 + lrow) * BS_STRIDE + wn * 64 + np * 16 + lcol);
                ldsm4t(b_h, baddr);
                ldsm4t(b_l, baddr + 2 * BS_PLANE);
#pragma unroll
                for (int mt = 0; mt < 2; mt++) {
                    mma_bf16(acc[mt][np * 2],     a_h[mt], b_h);
                    mma_bf16(acc[mt][np * 2],     a_l[mt], b_h);
                    mma_bf16(acc[mt][np * 2],     a_h[mt], b_l);
                    mma_bf16(acc[mt][np * 2 + 1], a_h[mt], b_h + 2);
                    mma_bf16(acc[mt][np * 2 + 1], a_l[mt], b_h + 2);
                    mma_bf16(acc[mt][np * 2 + 1], a_h[mt], b_l + 2);
                }
            }
        }
    }

    int g = lane >> 2, ti = lane & 3;
#pragma unroll
    for (int mt = 0; mt < 2; mt++) {
#pragma unroll
        for (int nt = 0; nt < 8; nt++) {
            float* c = acc[mt][nt];
            int row = m0 + wm * 32 + mt * 16 + g;
            int col = n0 + wn * 64 + nt * 8 + 2 * ti;
            if (MODE == 0) {
                float bv0 = bias[row], bv1 = bias[row + 8];
                *(float2*)(g_xp + (size_t)row * BB + col) = make_float2(c[0] + bv0, c[1] + bv0);
                *(float2*)(g_xp + (size_t)(row + 8) * BB + col) = make_float2(c[2] + bv1, c[3] + bv1);
            } else {
                float* base = g_part + (size_t)(blockIdx.z * BB) * ODP;
                base[(size_t)col * ODP + row] = c[0];
                base[(size_t)(col + 1) * ODP + row] = c[1];
                base[(size_t)col * ODP + row + 8] = c[2];
                base[(size_t)(col + 1) * ODP + row + 8] = c[3];
            }
        }
    }
}

// ---------------- step0: h = tanh(x_proj) ----------------
__global__ __launch_bounds__(256) void step0_kernel() {
    int i = blockIdx.x * 256 + threadIdx.x;
    g_h[0][i] = tanh_acc(g_xp[i]);
}

// ---------------- stencil step: 3-buffer rotation, no MOV window ----------------
__device__ __forceinline__ void stencil_x(
    int XI, int x0,
    const float4 (&P0)[9], const float4 (&P1)[9], float4 (&P2)[9],
    const float* sh, const int (&roff)[9], const float* wq,
    const float* xprow, float* horow)
{
    const int x = x0 + XI;
    float wv[28];
#pragma unroll
    for (int t = 0; t < 7; t++)
        *(float4*)(wv + t * 4) = *(const float4*)(wq + x * 28 + t * 4);
#pragma unroll
    for (int r = 0; r < 9; r++)
        P2[r] = *(const float4*)(sh + roff[r] + (x + 2) * 16);

    float4 s0 = make_float4(0.f, 0.f, 0.f, 0.f);
    float4 s1 = make_float4(0.f, 0.f, 0.f, 0.f);
    float4 s2 = make_float4(0.f, 0.f, 0.f, 0.f);
#pragma unroll
    for (int r = 0; r < 9; r++) {
        float w0 = wv[r * 3 + 0], w1 = wv[r * 3 + 1], w2 = wv[r * 3 + 2];
        s0.x = fmaf(w0, P0[r].x, s0.x); s0.y = fmaf(w0, P0[r].y, s0.y);
        s0.z = fmaf(w0, P0[r].z, s0.z); s0.w = fmaf(w0, P0[r].w, s0.w);
        s1.x = fmaf(w1, P1[r].x, s1.x); s1.y = fmaf(w1, P1[r].y, s1.y);
        s1.z = fmaf(w1, P1[r].z, s1.z); s1.w = fmaf(w1, P1[r].w, s1.w);
        s2.x = fmaf(w2, P2[r].x, s2.x); s2.y = fmaf(w2, P2[r].y, s2.y);
        s2.z = fmaf(w2, P2[r].z, s2.z); s2.w = fmaf(w2, P2[r].w, s2.w);
    }
    float4 xp = *(const float4*)(xprow + XI * BB);
    float4 o;
    o.x = tanh_acc(xp.x + s0.x + (s1.x + s2.x));
    o.y = tanh_acc(xp.y + s0.y + (s1.y + s2.y));
    o.z = tanh_acc(xp.z + s0.z + (s1.z + s2.z));
    o.w = tanh_acc(xp.w + s0.w + (s1.w + s2.w));
    *(float4*)(horow + XI * BB) = o;
}

__global__ __launch_bounds__(256, 1) void step_kernel(int src, const float* __restrict__ Wl) {
    const float* __restrict__ hin = g_h[src];
    float* __restrict__ hout = g_h[src ^ 1];

    extern __shared__ float dyn[];
    float* sh  = dyn;
    float* wsh = dyn + HALO_F;

    int tid = threadIdx.x;
    int y0 = blockIdx.x * 8;
    int z0 = blockIdx.y * 2;
    int b0 = blockIdx.z * 16;

    for (int i = tid; i < 4160; i += 256) {
        int q = i & 3; int site = i >> 2;
        int xx = site % 26; int t2 = site / 26;
        int yy = t2 % 10;   int zz = t2 / 10;
        int gx = xx - 1, gy = y0 + yy - 1, gz = z0 + zz - 1;
        float4 v = make_float4(0.f, 0.f, 0.f, 0.f);
        if ((unsigned)gx < (unsigned)CUBE && (unsigned)gy < (unsigned)CUBE &&
            (unsigned)gz < (unsigned)CUBE)
            v = *(const float4*)(hin + (gz * 576 + gy * 24 + gx) * BB + b0 + q * 4);
        *(float4*)(sh + zz * ZS + yy * YS + xx * 16 + q * 4) = v;
    }
    for (int i = tid; i < 16 * 648; i += 256) {
        int r = i / 648, j = i % 648;
        int x = j / 27, k = j % 27;
        int nr = (z0 + (r >> 3)) * 576 + (y0 + (r & 7)) * 24;
        wsh[r * WROW + x * 28 + k] = Wl[(nr + x) * 27 + k];
    }
    __syncthreads();

    int q  = tid & 3;
    int ry = (tid >> 2) & 7;
    int rz = (tid >> 5) & 1;
    int xq = tid >> 6;
    int x0 = xq * 6;

    int roff[9];
#pragma unroll
    for (int dz = 0; dz < 3; dz++)
#pragma unroll
        for (int dy = 0; dy < 3; dy++)
            roff[dz * 3 + dy] = (rz + dz) * ZS + (ry + dy) * YS + q * 4;

    float4 A[9], B[9], C[9];
#pragma unroll
    for (int r = 0; r < 9; r++) {
        A[r] = *(const float4*)(sh + roff[r] + x0 * 16);
        B[r] = *(const float4*)(sh + roff[r] + (x0 + 1) * 16);
    }

    int nrow = (z0 + rz) * 576 + (y0 + ry) * 24;
    const float* wq = wsh + (rz * 8 + ry) * WROW;
    const float* xprow = g_xp + (size_t)(nrow + x0) * BB + b0 + q * 4;
    float* horow = hout + (size_t)(nrow + x0) * BB + b0 + q * 4;

    stencil_x(0, x0, A, B, C, sh, roff, wq, xprow, horow);
    stencil_x(1, x0, B, C, A, sh, roff, wq, xprow, horow);
    stencil_x(2, x0, C, A, B, sh, roff, wq, xprow, horow);
    stencil_x(3, x0, A, B, C, sh, roff, wq, xprow, horow);
    stencil_x(4, x0, B, C, A, sh, roff, wq, xprow, horow);
    stencil_x(5, x0, C, A, B, sh, roff, wq, xprow, horow);
}

// ---------------- split h (after final step) ----------------
__global__ __launch_bounds__(256) void split_h_kernel() {
    int i = blockIdx.x * 256 + threadIdx.x;
    float v = g_h[1][i];
    __nv_bfloat16 h = __float2bfloat16_rn(v);
    g_hH[i] = h;
    g_hL[i] = __float2bfloat16_rn(v - __bfloat162float(h));
}

// ---------------- reduce partials + bias ----------------
__global__ __launch_bounds__(256) void reduce_kernel(const float* __restrict__ bo,
                                                     float* __restrict__ out) {
    int idx = blockIdx.x * 256 + threadIdx.x;
    if (idx >= BB * OD) return;
    int b = idx / OD, o = idx % OD;
    float s = bo[o];
#pragma unroll
    for (int sk = 0; sk < SK; sk++)
        s += g_part[(size_t)(sk * BB + b) * ODP + o];
    out[b * OD + o] = s;
}

// ---------------- launch ----------------
extern "C" void kernel_launch(void* const* d_in, const int* in_sizes, int n_in,
                              void* d_out, int out_size) {
    const float* x   = (const float*)d_in[0];
    const float* Wi  = (const float*)d_in[1];
    const float* bi  = (const float*)d_in[2];
    const float* Wl  = (const float*)d_in[3];
    const float* Wo  = (const float*)d_in[4];
    const float* bo  = (const float*)d_in[5];
    float* out = (float*)d_out;

    cudaFuncSetAttribute(step_kernel, cudaFuncAttributeMaxDynamicSharedMemorySize, STEP_SMEM);
    cudaFuncSetAttribute(mma_gemm<0>, cudaFuncAttributeMaxDynamicSharedMemorySize, GEMM_SMEM);
    cudaFuncSetAttribute(mma_gemm<1>, cudaFuncAttributeMaxDynamicSharedMemorySize, GEMM_SMEM);

    __nv_bfloat16 *winH, *winL, *woH, *woL, *xtH, *xtL, *hH, *hL;
    cudaGetSymbolAddress((void**)&winH, g_WinH);
    cudaGetSymbolAddress((void**)&winL, g_WinL);
    cudaGetSymbolAddress((void**)&woH, g_WoH);
    cudaGetSymbolAddress((void**)&woL, g_WoL);
    cudaGetSymbolAddress((void**)&xtH, g_xTH);
    cudaGetSymbolAddress((void**)&xtL, g_xTL);
    cudaGetSymbolAddress((void**)&hH, g_hH);
    cudaGetSymbolAddress((void**)&hL, g_hL);

    // conversions
    split_kernel<<<(NN * DIM + 255) / 256, 256>>>(Wi, winH, winL, NN * DIM);
    split_xT_kernel<<<(DIM * BB + 255) / 256, 256>>>(x);
    split_kernel<<<(OD * NN + 255) / 256, 256>>>(Wo, woH, woL, OD * NN);

    // x_proj via split-bf16 MMA
    mma_gemm<0><<<dim3(NN / 128, BB / 128, 1), 256, GEMM_SMEM>>>(
        winH, winL, xtH, xtL, bi, DIM, DIM / 64);

    step0_kernel<<<NN * BB / 256, 256>>>();

    int src = 0;
    for (int s = 0; s < 29; s++) {
        step_kernel<<<dim3(CUBE / 8, CUBE / 2, BB / 16), 256, STEP_SMEM>>>(src, Wl);
        src ^= 1;
    }

    split_h_kernel<<<NN * BB / 256, 256>>>();

    mma_gemm<1><<<dim3(ODP / 128, BB / 128, SK), 256, GEMM_SMEM>>>(
        woH, woL, hH, hL, nullptr, NN, KC / 64);
    reduce_kernel<<<(BB * OD + 255) / 256, 256>>>(bo, out);
}